// round 8
// baseline (speedup 1.0000x reference)
#include <cuda_runtime.h>
#include <cuda_bf16.h>

#define NN 100000
#define NE 1600000
#define CAP 64                // bucket capacity per node (max degree headroom)
#define DIN 256
#define DHID 64
#define DOUT 32

// ---------------- scratch (static device memory: allowed) ----------------
__device__ float  g_x0[NN * DOUT];
__device__ float  g_xa[NN * DOUT];
__device__ float  g_xb[NN * DOUT];
__device__ float2 g_cv[(size_t)NN * CAP];   // bucketed (col-as-int-bits, 0.9*val)
__device__ int    g_deg[NN];
__device__ int    g_bcnt[16];               // per-trip-count histogram
__device__ int    g_bcur[16];
__device__ int    g_order[NN];              // nodes sorted by trip count

// ---------------- fill: bucketed scatter ----------------
__global__ void k_fill(const int* __restrict__ row, const int* __restrict__ col,
                       const float* __restrict__ val) {
    int e = blockIdx.x * blockDim.x + threadIdx.x;
    if (e < NE) {
        int r = row[e];
        int idx = atomicAdd(&g_deg[r], 1);
        g_cv[(size_t)r * CAP + idx] = make_float2(__int_as_float(col[e]), 0.9f * val[e]);
    }
}

// zero padding tail to multiple of 8 + build trip-count histogram
__global__ void k_pad() {
    int i = blockIdx.x * blockDim.x + threadIdx.x;
    if (i < NN) {
        int d = g_deg[i];
        int dp = (d + 7) & ~7;
        float2* b = &g_cv[(size_t)i * CAP];
        for (int p = d; p < dp; p++) b[p] = make_float2(0.f, 0.f);
        atomicAdd(&g_bcnt[dp >> 3], 1);
    }
}

// tiny exclusive scan over 16 buckets (1 thread)
__global__ void k_binscan() {
    if (threadIdx.x == 0) {
        int run = 0;
        for (int t = 0; t < 16; t++) {
            g_bcur[t] = run;
            run += g_bcnt[t];
        }
    }
}

// scatter node ids into trip-sorted order
__global__ void k_scatter() {
    int i = blockIdx.x * blockDim.x + threadIdx.x;
    if (i < NN) {
        int t = ((g_deg[i] + 7) & ~7) >> 3;
        int pos = atomicAdd(&g_bcur[t], 1);
        g_order[pos] = i;
    }
}

// ---------------- MLP head: x0 = relu(F@W1 + b1)@W2 + b2 ----------------
#define FPAD 33
__global__ void __launch_bounds__(256)
k_mlp(const float* __restrict__ features,
      const float* __restrict__ W1, const float* __restrict__ b1,
      const float* __restrict__ W2, const float* __restrict__ b2) {
    extern __shared__ float sm[];
    float* w1s = sm;                      // 16384
    float* w2s = sm + 16384;              // 2048
    float* b1s = w2s + 2048;              // 64
    float* b2s = b1s + 64;                // 32
    float* fsm = b2s + 32;                // 256*33 = 8448

    const int t = threadIdx.x;
    const int node0 = blockIdx.x * 256;

    // fused init for the CSR build that follows
    {
        int gt = node0 + t;
        if (gt < NN) g_deg[gt] = 0;
        if (blockIdx.x == 0 && t < 16) g_bcnt[t] = 0;
    }

    for (int i = t; i < DIN * DHID; i += 256) w1s[i] = W1[i];
    for (int i = t; i < DHID * DOUT; i += 256) w2s[i] = W2[i];
    if (t < DHID) b1s[t] = b1[t];
    if (t < DOUT) b2s[t] = b2[t];
    __syncthreads();

    const float4* w1s4 = (const float4*)w1s;
    const float4* w2s4 = (const float4*)w2s;

    float acc[DHID];
    #pragma unroll
    for (int i = 0; i < DHID; i++) acc[i] = 0.f;

    for (int c = 0; c < DIN / 32; c++) {
        const int k0 = c * 32;
        __syncthreads();
        #pragma unroll
        for (int r = 0; r < 8; r++) {
            int lin = r * 256 + t;
            int nd = lin >> 3;
            int kg = lin & 7;
            float4 f4 = make_float4(0.f, 0.f, 0.f, 0.f);
            if (node0 + nd < NN)
                f4 = *(const float4*)&features[(size_t)(node0 + nd) * DIN + k0 + kg * 4];
            float* dst = &fsm[nd * FPAD + kg * 4];
            dst[0] = f4.x; dst[1] = f4.y; dst[2] = f4.z; dst[3] = f4.w;
        }
        __syncthreads();

        #pragma unroll 4
        for (int kk = 0; kk < 32; kk++) {
            float f = fsm[t * FPAD + kk];
            #pragma unroll
            for (int w = 0; w < 16; w++) {
                float4 wv = w1s4[(k0 + kk) * 16 + w];
                acc[w * 4 + 0] += f * wv.x;
                acc[w * 4 + 1] += f * wv.y;
                acc[w * 4 + 2] += f * wv.z;
                acc[w * 4 + 3] += f * wv.w;
            }
        }
    }

    #pragma unroll
    for (int i = 0; i < DHID; i++) {
        float z = acc[i] + b1s[i];
        acc[i] = z > 0.f ? z : 0.f;
    }

    for (int jg = 0; jg < 8; jg++) {
        float4 sv = ((const float4*)b2s)[jg];
        #pragma unroll
        for (int l = 0; l < DHID; l++) {
            float4 wv = w2s4[l * 8 + jg];
            float h = acc[l];
            sv.x += h * wv.x; sv.y += h * wv.y;
            sv.z += h * wv.z; sv.w += h * wv.w;
        }
        float* dst = &fsm[t * FPAD + jg * 4];
        dst[0] = sv.x; dst[1] = sv.y; dst[2] = sv.z; dst[3] = sv.w;
    }
    __syncthreads();

    #pragma unroll
    for (int r = 0; r < 8; r++) {
        int lin = r * 256 + t;
        int nd = lin >> 3;
        int jg = lin & 7;
        if (node0 + nd < NN) {
            float4 o;
            const float* src = &fsm[nd * FPAD + jg * 4];
            o.x = src[0]; o.y = src[1]; o.z = src[2]; o.w = src[3];
            *(float4*)&g_x0[(size_t)(node0 + nd) * DOUT + jg * 4] = o;
        }
    }
}

// ---------------- propagation: dst = (A' @ src) + 0.1 * x0  (0.9 folded into A') ------
// 4 trip-sorted nodes per warp (grp = lane>>3, lane8 = lane&7 → 32 cols via float4).
// Rolled trip loop with next-descriptor prefetch; sentinel edges gather row 0.
// NO reg cap — spills in the hot loop cost more than occupancy buys (R3 lesson).
__global__ void __launch_bounds__(256)
k_spmm(const float* __restrict__ xsrc, float* __restrict__ xdst) {
    int gtid  = blockIdx.x * blockDim.x + threadIdx.x;
    int warp  = gtid >> 5;
    int lane  = threadIdx.x & 31;
    int grp   = lane >> 3;
    int lane8 = lane & 7;
    int slot  = warp * 4 + grp;
    if (slot >= NN) return;
    int node = g_order[slot];            // trip-sorted → quad has (near-)equal trips

    int trip = (g_deg[node] + 7) >> 3;
    int mt = trip;
    mt = max(mt, __shfl_xor_sync(0xffffffffu, mt, 16));
    mt = max(mt, __shfl_xor_sync(0xffffffffu, mt, 8));

    const float2* __restrict__ bucket = &g_cv[(size_t)node * CAP];

    float4 acc = make_float4(0.f, 0.f, 0.f, 0.f);
    float2 cv = make_float2(0.f, 0.f);
    if (0 < trip) cv = __ldg(&bucket[lane8]);

    for (int t = 0; t < mt; t++) {
        float2 nv = make_float2(0.f, 0.f);
        if (t + 1 < trip) nv = __ldg(&bucket[lane8 + 8 * (t + 1)]);
        #pragma unroll
        for (int j = 0; j < 8; j++) {
            int   c = __float_as_int(__shfl_sync(0xffffffffu, cv.x, (lane & 24) + j));
            float v = __shfl_sync(0xffffffffu, cv.y, (lane & 24) + j);
            float4 g = __ldg((const float4*)&xsrc[(size_t)c * DOUT + lane8 * 4]);
            acc.x += v * g.x;
            acc.y += v * g.y;
            acc.z += v * g.z;
            acc.w += v * g.w;
        }
        cv = nv;
    }

    const float4 x0 = *(const float4*)&g_x0[(size_t)node * DOUT + lane8 * 4];
    float4 o;
    o.x = acc.x + 0.1f * x0.x;
    o.y = acc.y + 0.1f * x0.y;
    o.z = acc.z + 0.1f * x0.z;
    o.w = acc.w + 0.1f * x0.w;
    *(float4*)&xdst[(size_t)node * DOUT + lane8 * 4] = o;
}

// ---------------- launch ----------------
extern "C" void kernel_launch(void* const* d_in, const int* in_sizes, int n_in,
                              void* d_out, int out_size) {
    const float* features = (const float*)d_in[0];
    const int*   row      = (const int*)d_in[1];
    const int*   col      = (const int*)d_in[2];
    const float* vals     = (const float*)d_in[3];
    const float* W1       = (const float*)d_in[4];
    const float* b1       = (const float*)d_in[5];
    const float* W2       = (const float*)d_in[6];
    const float* b2       = (const float*)d_in[7];

    float *x0p, *xap, *xbp;
    cudaGetSymbolAddress((void**)&x0p, g_x0);
    cudaGetSymbolAddress((void**)&xap, g_xa);
    cudaGetSymbolAddress((void**)&xbp, g_xb);

    // 1) MLP head (also zeroes degree counters + bucket histogram)
    const int smem_bytes = (16384 + 2048 + 64 + 32 + 256 * FPAD) * sizeof(float);
    cudaFuncSetAttribute(k_mlp, cudaFuncAttributeMaxDynamicSharedMemorySize, smem_bytes);
    k_mlp<<<(NN + 255) / 256, 256, smem_bytes>>>(features, W1, b1, W2, b2);

    // 2) bucketed CSR build, pad, trip-count sort  (launches 2..5)
    k_fill<<<(NE + 255) / 256, 256>>>(row, col, vals);
    k_pad<<<(NN + 255) / 256, 256>>>();
    k_binscan<<<1, 32>>>();
    k_scatter<<<(NN + 255) / 256, 256>>>();

    // 6..15) 10 propagation steps, ping-pong; last writes d_out
    // (launch #6 = first k_spmm → ncu -s 5 -c 1 captures the hot kernel)
    const int spmm_blocks = (NN / 4 * 32 + 255) / 256;   // 4 nodes per warp
    const float* src = x0p;
    for (int it = 0; it < 10; it++) {
        float* dst = (it == 9) ? (float*)d_out : ((it % 2 == 0) ? xap : xbp);
        k_spmm<<<spmm_blocks, 256>>>(src, dst);
        src = dst;
    }
}

// round 12
// speedup vs baseline: 1.9940x; 1.9940x over previous
#include <cuda_runtime.h>
#include <cuda_bf16.h>
#include <cstdint>

#define NN 100000
#define NE 1600000
#define CAP 64                // bucket capacity per node (max degree headroom)
#define DIN 256
#define DHID 64
#define DOUT 32

// ---------------- scratch (static device memory: allowed) ----------------
__device__ float  g_x0[NN * DOUT];
__device__ float  g_xa[NN * DOUT];
__device__ float  g_xb[NN * DOUT];
__device__ float2 g_cv[(size_t)NN * CAP];   // bucketed (col-as-int-bits, 0.9*val)
__device__ int    g_deg[NN];

// ---------------- fill: bucketed scatter ----------------
__global__ void k_fill(const int* __restrict__ row, const int* __restrict__ col,
                       const float* __restrict__ val) {
    int e = blockIdx.x * blockDim.x + threadIdx.x;
    if (e < NE) {
        int r = row[e];
        int idx = atomicAdd(&g_deg[r], 1);
        g_cv[(size_t)r * CAP + idx] = make_float2(__int_as_float(col[e]), 0.9f * val[e]);
    }
}

// zero the padding tail (deg .. round8(deg)-1) with (col=0, val=0) sentinels
__global__ void k_pad() {
    int i = blockIdx.x * blockDim.x + threadIdx.x;
    if (i < NN) {
        int d = g_deg[i];
        int dp = (d + 7) & ~7;
        float2* b = &g_cv[(size_t)i * CAP];
        for (int p = d; p < dp; p++) b[p] = make_float2(0.f, 0.f);
    }
}

// ---------------- MLP head: x0 = relu(F@W1 + b1)@W2 + b2 ----------------
// Layer 1 on tf32 tensor cores (mma.sync m16n8k8). Block = 256 thr = 8 warps,
// 128 nodes/block, warp handles an m16 x n64 tile over K=256.
// W1 pre-staged fragment-ordered in smem (B-frag = one conflict-free LDS.64).
// Layer 2 (64x32) stays scalar fp32 through an smem round-trip of H.

__device__ __forceinline__ uint32_t f2tf32(float f) {
    uint32_t u;
    asm("cvt.rna.tf32.f32 %0, %1;" : "=r"(u) : "f"(f));
    return u;
}

// smem byte offsets
#define SM_W2    0                       // 64*32 floats  = 8192 B
#define SM_B1    8192                    // 64 floats     = 256 B
#define SM_B2    8448                    // 32 floats     = 128 B
#define SM_BFRAG 8704                    // 8192 uint2    = 65536 B
#define SM_FCH   (8704 + 65536)          // 128*33 uint   = 16896 B
#define SM_HS    8704                    // ALIAS of BFRAG: 128*68 floats = 34816 B
#define SM_TOTAL (SM_FCH + 16896)        // 91136 B

__global__ void __launch_bounds__(256)
k_mlp(const float* __restrict__ features,
      const float* __restrict__ W1, const float* __restrict__ b1,
      const float* __restrict__ W2, const float* __restrict__ b2) {
    extern __shared__ char smraw[];
    float*    w2s   = (float*)(smraw + SM_W2);
    float*    b1s   = (float*)(smraw + SM_B1);
    float*    b2s   = (float*)(smraw + SM_B2);
    uint2*    bfrag = (uint2*)(smraw + SM_BFRAG);
    uint32_t* fch   = (uint32_t*)(smraw + SM_FCH);
    float*    hs    = (float*)(smraw + SM_HS);

    const int tid   = threadIdx.x;
    const int lane  = tid & 31;
    const int wid   = tid >> 5;
    const int node0 = blockIdx.x * 128;

    // fused init for the CSR build that follows
    if (tid < 128 && node0 + tid < NN) g_deg[node0 + tid] = 0;

    // stage W2 / biases
    for (int i = tid; i < DHID * DOUT; i += 256) w2s[i] = W2[i];
    if (tid < DHID) b1s[tid] = b1[tid];
    if (tid < DOUT) b2s[tid] = b2[tid];

    // stage W1 fragment-ordered, tf32-converted:
    // bfrag[(kstep*8 + nt)*32 + lane] = { W1[k][n], W1[k+4][n] },
    //   k = kstep*8 + (lane&3), n = nt*8 + (lane>>2), kstep in [0,32)
    for (int i = tid; i < 8192; i += 256) {
        int kstep = i >> 8;
        int rem   = i & 255;
        int nt    = rem >> 5;
        int ln    = rem & 31;
        int k     = kstep * 8 + (ln & 3);
        int n     = nt * 8 + (ln >> 2);
        uint32_t t0 = f2tf32(W1[k * DHID + n]);
        uint32_t t1 = f2tf32(W1[(k + 4) * DHID + n]);
        bfrag[i] = make_uint2(t0, t1);
    }
    __syncthreads();

    float c[8][4];
    #pragma unroll
    for (int nt = 0; nt < 8; nt++)
        #pragma unroll
        for (int j = 0; j < 4; j++) c[nt][j] = 0.f;

    const int rw = wid * 16;             // warp's row base within block
    const int r4 = lane >> 2;            // 0..7
    const int q4 = lane & 3;             // 0..3

    for (int ch = 0; ch < 8; ch++) {     // K chunks of 32
        const int k0 = ch * 32;
        __syncthreads();                 // protect fch reuse
        // stage F chunk: 128 rows x 32 k, tf32-converted, stride 33
        #pragma unroll
        for (int r = 0; r < 4; r++) {
            int lin = r * 256 + tid;     // 1024 float4 slots
            int rowi = lin >> 3;
            int qq   = lin & 7;
            float4 f4 = make_float4(0.f, 0.f, 0.f, 0.f);
            if (node0 + rowi < NN)
                f4 = *(const float4*)&features[(size_t)(node0 + rowi) * DIN + k0 + qq * 4];
            uint32_t* dst = &fch[rowi * 33 + qq * 4];
            dst[0] = f2tf32(f4.x); dst[1] = f2tf32(f4.y);
            dst[2] = f2tf32(f4.z); dst[3] = f2tf32(f4.w);
        }
        __syncthreads();

        #pragma unroll
        for (int kk = 0; kk < 4; kk++) {
            uint32_t a0 = fch[(rw + r4) * 33 + kk * 8 + q4];
            uint32_t a1 = fch[(rw + r4 + 8) * 33 + kk * 8 + q4];
            uint32_t a2 = fch[(rw + r4) * 33 + kk * 8 + q4 + 4];
            uint32_t a3 = fch[(rw + r4 + 8) * 33 + kk * 8 + q4 + 4];
            const int ks = ch * 4 + kk;
            #pragma unroll
            for (int nt = 0; nt < 8; nt++) {
                uint2 bb = bfrag[(ks * 8 + nt) * 32 + lane];
                asm volatile(
                    "mma.sync.aligned.m16n8k8.row.col.f32.tf32.tf32.f32 "
                    "{%0,%1,%2,%3}, {%4,%5,%6,%7}, {%8,%9}, {%0,%1,%2,%3};"
                    : "+f"(c[nt][0]), "+f"(c[nt][1]), "+f"(c[nt][2]), "+f"(c[nt][3])
                    : "r"(a0), "r"(a1), "r"(a2), "r"(a3), "r"(bb.x), "r"(bb.y));
            }
        }
    }

    __syncthreads();   // all bfrag reads done before aliased H stores

    // bias + relu, store H tile (stride 68) for layer 2
    #pragma unroll
    for (int nt = 0; nt < 8; nt++) {
        int col = nt * 8 + 2 * q4;
        float bA = b1s[col], bB = b1s[col + 1];
        float h0 = fmaxf(c[nt][0] + bA, 0.f);
        float h1 = fmaxf(c[nt][1] + bB, 0.f);
        float h2 = fmaxf(c[nt][2] + bA, 0.f);
        float h3 = fmaxf(c[nt][3] + bB, 0.f);
        float2* p0 = (float2*)&hs[(rw + r4) * 68 + col];
        float2* p1 = (float2*)&hs[(rw + r4 + 8) * 68 + col];
        *p0 = make_float2(h0, h1);
        *p1 = make_float2(h2, h3);
    }
    __syncthreads();

    // layer 2: 2 threads per node, each does 16 output cols
    {
        int nodel = tid >> 1;
        int half  = tid & 1;
        int node  = node0 + nodel;
        const float4* hp  = (const float4*)&hs[nodel * 68];
        const float4* w2p = (const float4*)w2s;
        float4 o0 = ((const float4*)b2s)[half * 4 + 0];
        float4 o1 = ((const float4*)b2s)[half * 4 + 1];
        float4 o2 = ((const float4*)b2s)[half * 4 + 2];
        float4 o3 = ((const float4*)b2s)[half * 4 + 3];
        #pragma unroll 4
        for (int k4 = 0; k4 < 16; k4++) {
            float4 h4 = hp[k4];
            float hv[4] = {h4.x, h4.y, h4.z, h4.w};
            #pragma unroll
            for (int s = 0; s < 4; s++) {
                int l = k4 * 4 + s;
                float h = hv[s];
                float4 wv0 = w2p[l * 8 + half * 4 + 0];
                float4 wv1 = w2p[l * 8 + half * 4 + 1];
                float4 wv2 = w2p[l * 8 + half * 4 + 2];
                float4 wv3 = w2p[l * 8 + half * 4 + 3];
                o0.x += h * wv0.x; o0.y += h * wv0.y; o0.z += h * wv0.z; o0.w += h * wv0.w;
                o1.x += h * wv1.x; o1.y += h * wv1.y; o1.z += h * wv1.z; o1.w += h * wv1.w;
                o2.x += h * wv2.x; o2.y += h * wv2.y; o2.z += h * wv2.z; o2.w += h * wv2.w;
                o3.x += h * wv3.x; o3.y += h * wv3.y; o3.z += h * wv3.z; o3.w += h * wv3.w;
            }
        }
        if (node < NN) {
            float4* out = (float4*)&g_x0[(size_t)node * DOUT + half * 16];
            out[0] = o0; out[1] = o1; out[2] = o2; out[3] = o3;
        }
    }
}

// ---------------- propagation: dst = (A' @ src) + 0.1 * x0  (0.9 folded into A') ------
// EXACT R2 version (432 us config, 29.3 us/iter measured). 4 nodes per warp.
__global__ void __launch_bounds__(256)
k_spmm(const float* __restrict__ xsrc, float* __restrict__ xdst) {
    int gtid  = blockIdx.x * blockDim.x + threadIdx.x;
    int warp  = gtid >> 5;
    int lane  = threadIdx.x & 31;
    int grp   = lane >> 3;
    int lane8 = lane & 7;
    int node  = warp * 4 + grp;
    if (node >= NN) return;

    int trip = (g_deg[node] + 7) >> 3;
    int mt = trip;
    mt = max(mt, __shfl_xor_sync(0xffffffffu, mt, 16));
    mt = max(mt, __shfl_xor_sync(0xffffffffu, mt, 8));

    const float2* __restrict__ bucket = &g_cv[(size_t)node * CAP];
    int p = lane8;

    float4 acc = make_float4(0.f, 0.f, 0.f, 0.f);
    for (int t = 0; t < mt; t++) {
        float2 cv = make_float2(0.f, 0.f);
        if (t < trip) cv = __ldg(&bucket[p]);
        p += 8;
        #pragma unroll
        for (int j = 0; j < 8; j++) {
            int   col = __float_as_int(__shfl_sync(0xffffffffu, cv.x, (lane & 24) + j));
            float v   = __shfl_sync(0xffffffffu, cv.y, (lane & 24) + j);
            float4 g = __ldg((const float4*)&xsrc[(size_t)col * DOUT + lane8 * 4]);
            acc.x += v * g.x;
            acc.y += v * g.y;
            acc.z += v * g.z;
            acc.w += v * g.w;
        }
    }

    const float4 x0 = *(const float4*)&g_x0[(size_t)node * DOUT + lane8 * 4];
    float4 o;
    o.x = acc.x + 0.1f * x0.x;
    o.y = acc.y + 0.1f * x0.y;
    o.z = acc.z + 0.1f * x0.z;
    o.w = acc.w + 0.1f * x0.w;
    *(float4*)&xdst[(size_t)node * DOUT + lane8 * 4] = o;
}

// ---------------- launch ----------------
extern "C" void kernel_launch(void* const* d_in, const int* in_sizes, int n_in,
                              void* d_out, int out_size) {
    const float* features = (const float*)d_in[0];
    const int*   row      = (const int*)d_in[1];
    const int*   col      = (const int*)d_in[2];
    const float* vals     = (const float*)d_in[3];
    const float* W1       = (const float*)d_in[4];
    const float* b1       = (const float*)d_in[5];
    const float* W2       = (const float*)d_in[6];
    const float* b2       = (const float*)d_in[7];

    float *x0p, *xap, *xbp;
    cudaGetSymbolAddress((void**)&x0p, g_x0);
    cudaGetSymbolAddress((void**)&xap, g_xa);
    cudaGetSymbolAddress((void**)&xbp, g_xb);

    // 1) MLP head (tf32 tensor cores; also zeroes degree counters)
    cudaFuncSetAttribute(k_mlp, cudaFuncAttributeMaxDynamicSharedMemorySize, SM_TOTAL);
    k_mlp<<<(NN + 127) / 128, 256, SM_TOTAL>>>(features, W1, b1, W2, b2);

    // 2) bucketed CSR build + 3) pad tails to multiple of 8
    k_fill<<<(NE + 255) / 256, 256>>>(row, col, vals);
    k_pad<<<(NN + 255) / 256, 256>>>();

    // 4..13) 10 propagation steps, ping-pong; last writes d_out
    const int spmm_blocks = (NN / 4 * 32 + 255) / 256;   // 4 nodes per warp
    const float* src = x0p;
    for (int it = 0; it < 10; it++) {
        float* dst = (it == 9) ? (float*)d_out : ((it % 2 == 0) ? xap : xbp);
        k_spmm<<<spmm_blocks, 256>>>(src, dst);
        src = dst;
    }
}